// round 15
// baseline (speedup 1.0000x reference)
#include <cuda_runtime.h>
#include <cstdint>
#include <math.h>

#define B     64
#define T     256
#define U     1024
#define G3    3072
#define NBLK  128
#define NT    512
#define NFLAG 4

// h packed as int8 limbs in m16n8k32 A-fragment order:
// [par][ ((bt*32 + kc)*2 + limb)*32 + lane ] -> uint4 (16 bytes = a0..a3 frags)
__device__ __align__(16) uint4 g_hpk[2][4 * 32 * 2 * 32];
// per k-quarter dependency counters, 128B apart
__device__ __align__(128) unsigned g_flag[NFLAG * 32];
__device__ unsigned g_bar_cnt, g_bar_gen;

// ---- SMEM layout (bytes) ----
// W limbs: [kc 32][n 24] rows of 80B: [w0 k0..31 (32B)][w1 k0..31 (32B)][pad 16B]
#define SM_W     0
#define W_KCSTR  1920              // 24 * 80
#define SM_REC   61440             // float [4 plane][64][26]
#define REC_PL   1664
#define SMEM_TOTAL (61440 + 4*6656) // 88064

// scales: h = (a + b/254)/24 ; W = (w0 + w1/254)/4064
#define SH    24.0f
#define SW    4064.0f
#define INV254 (1.0f/254.0f)
#define INVS  (1.0f/(24.0f*4064.0f))

// ---- PTX helpers ----
__device__ __forceinline__ void mma8(int* c, const uint4& a, uint32_t b0, uint32_t b1) {
    asm volatile("mma.sync.aligned.m16n8k32.row.col.s32.s8.s8.s32 "
                 "{%0,%1,%2,%3}, {%4,%5,%6,%7}, {%8,%9}, {%0,%1,%2,%3};"
                 : "+r"(c[0]), "+r"(c[1]), "+r"(c[2]), "+r"(c[3])
                 : "r"(a.x), "r"(a.y), "r"(a.z), "r"(a.w), "r"(b0), "r"(b1));
}
__device__ __forceinline__ void wait_flag(unsigned* f, unsigned tgt) {
    unsigned g;
    while (1) {
        asm volatile("ld.acquire.gpu.u32 %0, [%1];" : "=r"(g) : "l"(f));
        if ((int)(g - tgt) >= 0) break;
        __nanosleep(32);
    }
}
__device__ __forceinline__ void arrive_flag(unsigned* f) {
    asm volatile("red.release.gpu.global.add.u32 [%0], 1;" :: "l"(f));
}
__device__ __forceinline__ void grid_barrier() {
    __syncthreads();
    if (threadIdx.x == 0) {
        unsigned gen0;
        asm volatile("ld.acquire.gpu.u32 %0, [%1];" : "=r"(gen0) : "l"(&g_bar_gen));
        unsigned prev;
        asm volatile("atom.release.gpu.global.add.u32 %0, [%1], 1;" : "=r"(prev) : "l"(&g_bar_cnt));
        if (prev == NBLK - 1) {
            asm volatile("st.relaxed.gpu.global.u32 [%0], 0;" :: "l"(&g_bar_cnt));
            asm volatile("red.release.gpu.global.add.u32 [%0], 1;" :: "l"(&g_bar_gen));
        } else {
            unsigned g;
            do { asm volatile("ld.acquire.gpu.u32 %0, [%1];" : "=r"(g) : "l"(&g_bar_gen)); } while (g == gen0);
        }
    }
    __syncthreads();
}

// pack one unit's h into int8 limbs at precomputed byte offset (limb b at +512)
__device__ __forceinline__ void pack_h(int buf, uint32_t poff, float h) {
    float t = h * SH;
    int ai = __float2int_rn(t);
    ai = max(-127, min(127, ai));
    int bi = __float2int_rn((t - (float)ai) * 254.0f);
    char* base = (char*)g_hpk[buf];
    base[poff]       = (char)ai;
    base[poff + 512] = (char)bi;
}

__global__ void __launch_bounds__(NT, 1)
gru_all(const int* __restrict__ x, const float* __restrict__ hidden,
        const float* __restrict__ Win, const float* __restrict__ Wrec,
        const float* __restrict__ bin, const float* __restrict__ brec,
        float* __restrict__ out) {
    extern __shared__ __align__(1024) char smem[];
    float* rec_s = (float*)(smem + SM_REC);
    const int tid = threadIdx.x;
    const int wid = tid >> 5;
    const int l   = tid & 31;
    const int blk = blockIdx.x;
    const int u0  = blk * 8;

    // ---- one-time: W_rec slice -> int8 limbs in SMEM ----
    for (int idx = tid; idx < 24 * U; idx += NT) {
        int k = idx / 24;
        int j = idx - k * 24;          // n = j : gate = j>>3, unit = j&7
        int gate = j >> 3, uun = j & 7;
        float w = Wrec[(size_t)k * G3 + gate * U + u0 + uun];
        float t = w * SW;
        int w0 = __float2int_rn(t);
        w0 = max(-127, min(127, w0));
        int w1 = __float2int_rn((t - (float)w0) * 254.0f);
        int kc = k >> 5, kk = k & 31;
        char* row = smem + SM_W + kc * W_KCSTR + j * 80;
        row[kk]      = (char)w0;
        row[32 + kk] = (char)w1;
    }

    // ---- gate mapping: 512 threads, 1 unit each: (b, uu) ----
    const int b  = tid >> 3;
    const int uu = tid & 7;
    const float cz  = bin[0 * U + u0 + uu] + brec[0 * U + u0 + uu];
    const float cr  = bin[1 * U + u0 + uu] + brec[1 * U + u0 + uu];
    const float bih = bin[2 * U + u0 + uu];
    const float bhh = brec[2 * U + u0 + uu];
    float hold = hidden[(size_t)b * U + u0 + uu];
    int tok = x[b * T];

    // pack offset for this thread's unit (A fragment layout of m16n8k32)
    const int kc_self = blk >> 2;
    const int bt_self = b >> 4;
    const int row_    = b & 15;
    const int k32     = (blk & 3) * 8 + uu;                 // k within 32-chunk
    const int lane_   = (row_ & 7) * 4 + ((k32 & 15) >> 2);
    const int reg_    = ((row_ >> 3) & 1) + ((k32 >> 4) << 1);
    const uint32_t poff = (uint32_t)(((bt_self * 32 + kc_self) * 2 + 0) * 32 + lane_) * 16
                        + reg_ * 4 + (k32 & 3);

    // ---- warp MMA mapping: 16 warps = 4 kq-quarters x 4 batch-tiles ----
    const int kq  = wid >> 2;     // k-quarter (8 kc = 256 k)
    const int btw = wid & 3;      // batch-tile
    const int kc0 = kq * 8;
    const int grp = blk >> 5;     // producer flag group (32 CTAs per quarter)

    unsigned fbase = *(volatile unsigned*)&g_flag[kq * 32];
    grid_barrier();

    // ---- preload w0 fragments into registers (loop-invariant) ----
    // B-frag lane mapping: n = nt*8 + (l>>2), k bytes (l&3)*4.. ; reg half rh: k += 16*rh
    uint32_t w0r[8][3][2];
    #pragma unroll
    for (int kcl = 0; kcl < 8; kcl++) {
        const char* wrow = smem + SM_W + (kc0 + kcl) * W_KCSTR + (l >> 2) * 80 + (l & 3) * 4;
        #pragma unroll
        for (int nt = 0; nt < 3; nt++) {
            w0r[kcl][nt][0] = *(const uint32_t*)(wrow + nt * 640);
            w0r[kcl][nt][1] = *(const uint32_t*)(wrow + nt * 640 + 16);
        }
    }

    // publish h0 into buffer 0
    pack_h(0, poff, hold);
    __syncthreads();
    if (tid == 0) arrive_flag(&g_flag[grp * 32]);

    for (int t = 0; t < T; t++) {
        const int par = t & 1;

        // gate-input loads issued before the flag wait
        const float* wrow = Win + (size_t)tok * G3 + u0 + uu;
        float xz = wrow[0], xr = wrow[U], xh = wrow[2 * U];
        int tok_n = (t + 1 < T) ? x[b * T + t + 1] : 0;

        // wait for the 32 producer CTAs of this warp's k-quarter
        if (l == 0) wait_flag(&g_flag[kq * 32], fbase + 32u * (t + 1));
        __syncwarp();

        // ---- GEMM: 8 k-chunks (k32 each), 1 batch-tile, 3 int8 terms ----
        int acc0[3][4], acc1[3][4];
        #pragma unroll
        for (int nt = 0; nt < 3; nt++)
            #pragma unroll
            for (int e = 0; e < 4; e++) { acc0[nt][e] = 0; acc1[nt][e] = 0; }

        const uint4* pA = g_hpk[par] + (size_t)((btw * 32 + kc0) * 2) * 32 + l;

        uint4 Aa[2], Ab[2];
        Aa[0] = __ldcg(pA);        Ab[0] = __ldcg(pA + 32);
        Aa[1] = __ldcg(pA + 64);   Ab[1] = __ldcg(pA + 96);

        #pragma unroll
        for (int kcl = 0; kcl < 8; kcl++) {
            uint4 ca = Aa[kcl & 1], cb = Ab[kcl & 1];
            if (kcl < 6) {
                Aa[kcl & 1] = __ldcg(pA + (kcl + 2) * 64);
                Ab[kcl & 1] = __ldcg(pA + (kcl + 2) * 64 + 32);
            }
            // w1 fragments for this kc
            const char* w1row = smem + SM_W + (kc0 + kcl) * W_KCSTR
                              + (l >> 2) * 80 + (l & 3) * 4 + 32;
            uint32_t w1[3][2];
            #pragma unroll
            for (int nt = 0; nt < 3; nt++) {
                w1[nt][0] = *(const uint32_t*)(w1row + nt * 640);
                w1[nt][1] = *(const uint32_t*)(w1row + nt * 640 + 16);
            }
            // term a@w0 (3 independent chains)
            mma8(acc0[0], ca, w0r[kcl][0][0], w0r[kcl][0][1]);
            mma8(acc0[1], ca, w0r[kcl][1][0], w0r[kcl][1][1]);
            mma8(acc0[2], ca, w0r[kcl][2][0], w0r[kcl][2][1]);
            // term a@w1
            mma8(acc1[0], ca, w1[0][0], w1[0][1]);
            mma8(acc1[1], ca, w1[1][0], w1[1][1]);
            mma8(acc1[2], ca, w1[2][0], w1[2][1]);
            // term b@w0 (same scale as a@w1 -> same accumulator)
            mma8(acc1[0], cb, w0r[kcl][0][0], w0r[kcl][0][1]);
            mma8(acc1[1], cb, w0r[kcl][1][0], w0r[kcl][1][1]);
            mma8(acc1[2], cb, w0r[kcl][2][0], w0r[kcl][2][1]);
        }

        // ---- epilogue: dequant + store partials -> plane kq ----
        {
            float* pl = rec_s + kq * REC_PL;
            int row = l >> 2, c2 = (l & 3) * 2;
            int bb0 = btw * 16 + row;
            #pragma unroll
            for (int nt = 0; nt < 3; nt++) {
                float r0 = ((float)acc0[nt][0] + (float)acc1[nt][0] * INV254) * INVS;
                float r1 = ((float)acc0[nt][1] + (float)acc1[nt][1] * INV254) * INVS;
                float r2 = ((float)acc0[nt][2] + (float)acc1[nt][2] * INV254) * INVS;
                float r3 = ((float)acc0[nt][3] + (float)acc1[nt][3] * INV254) * INVS;
                int j0 = nt * 8 + c2;
                *(float2*)&pl[bb0 * 26 + j0]       = make_float2(r0, r1);
                *(float2*)&pl[(bb0 + 8) * 26 + j0] = make_float2(r2, r3);
            }
        }
        __syncthreads();

        // ---- gates: every thread, 1 unit ----
        {
            float rz = cz, rr = cr, rh = bhh;
            #pragma unroll
            for (int p = 0; p < 4; p++) {
                const float* pl = rec_s + p * REC_PL + b * 26;
                rz += pl[uu];
                rr += pl[8 + uu];
                rh += pl[16 + uu];
            }
            float z  = __fdividef(1.f, 1.f + __expf(-(xz + rz)));
            float r  = __fdividef(1.f, 1.f + __expf(-(xr + rr)));
            float ta = xh + bih + r * rh;
            float hh = 1.f - __fdividef(2.f, __expf(2.f * ta) + 1.f);
            float hn = z * hold + (1.f - z) * hh;
            hold = hn;
            pack_h(par ^ 1, poff, hn);
            __syncthreads();
            if (tid == 0 && t < T - 1) arrive_flag(&g_flag[grp * 32]);
            out[((size_t)b * T + t) * U + u0 + uu] = hn;
            if (t == T - 1)
                out[(size_t)B * T * U + (size_t)b * U + u0 + uu] = hn;
            tok = tok_n;
        }
    }
}

extern "C" void kernel_launch(void* const* d_in, const int* in_sizes, int n_in,
                              void* d_out, int out_size) {
    const int*   x      = (const int*)d_in[0];
    const float* hidden = (const float*)d_in[1];
    const float* Win    = (const float*)d_in[2];
    const float* Wrec   = (const float*)d_in[3];
    const float* bin    = (const float*)d_in[4];
    const float* brec   = (const float*)d_in[5];
    float* out = (float*)d_out;

    cudaFuncSetAttribute(gru_all, cudaFuncAttributeMaxDynamicSharedMemorySize, SMEM_TOTAL);
    gru_all<<<NBLK, NT, SMEM_TOTAL>>>(x, hidden, Win, Wrec, bin, brec, out);
}

// round 16
// speedup vs baseline: 2.3815x; 2.3815x over previous
#include <cuda_runtime.h>
#include <cuda_bf16.h>
#include <cstdint>
#include <math.h>

#define B     64
#define T     256
#define U     1024
#define G3    3072
#define NBLK  128
#define NT    512

// h packed in MMA A-fragment order:
// [par][ ((bt*64 + kk)*2 + half)*32 + lane ] -> uint4
__device__ __align__(16) uint4 g_hpk[2][4 * 64 * 2 * 32];
// flags[kq][bth]: 16 counters, 128B apart (one L2 line each)
__device__ __align__(128) unsigned g_flag[16 * 32];
__device__ unsigned g_bar_cnt, g_bar_gen;

// ---- SMEM layout (bytes) ----
#define SM_W      0
#define W_NSTR    2064
#define W_PSTR    49536
#define SM_REC    99072              // [2 group][8 plane][32 row][26 f]
#define REC_GRP   26624              // bytes per group region
#define REC_PL    832                // floats per plane (32*26)
#define SMEM_TOTAL (99072 + 2*26624) // 152320

// ---- PTX helpers ----
__device__ __forceinline__ uint32_t smem_u32(const void* p) {
    uint32_t a;
    asm("{ .reg .u64 t; cvta.to.shared.u64 t, %1; cvt.u32.u64 %0, t; }" : "=r"(a) : "l"(p));
    return a;
}
__device__ __forceinline__ void ldsm2(uint32_t* r, uint32_t addr) {
    asm volatile("ldmatrix.sync.aligned.m8n8.x2.shared.b16 {%0,%1}, [%2];"
                 : "=r"(r[0]), "=r"(r[1]) : "r"(addr));
}
__device__ __forceinline__ void ldsm4(uint32_t* r, uint32_t addr) {
    asm volatile("ldmatrix.sync.aligned.m8n8.x4.shared.b16 {%0,%1,%2,%3}, [%4];"
                 : "=r"(r[0]), "=r"(r[1]), "=r"(r[2]), "=r"(r[3]) : "r"(addr));
}
__device__ __forceinline__ void mma4(float* c, const uint4& a, uint32_t b0, uint32_t b1) {
    asm volatile("mma.sync.aligned.m16n8k16.row.col.f32.bf16.bf16.f32 "
                 "{%0,%1,%2,%3}, {%4,%5,%6,%7}, {%8,%9}, {%0,%1,%2,%3};"
                 : "+f"(c[0]), "+f"(c[1]), "+f"(c[2]), "+f"(c[3])
                 : "r"(a.x), "r"(a.y), "r"(a.z), "r"(a.w), "r"(b0), "r"(b1));
}
__device__ __forceinline__ void wait_flag(unsigned* f, unsigned tgt) {
    unsigned g;
    while (1) {
        asm volatile("ld.acquire.gpu.u32 %0, [%1];" : "=r"(g) : "l"(f));
        if ((int)(g - tgt) >= 0) break;
        __nanosleep(32);
    }
}
__device__ __forceinline__ void arrive_flag(unsigned* f) {
    asm volatile("red.release.gpu.global.add.u32 [%0], 1;" :: "l"(f));
}
__device__ __forceinline__ void grid_barrier() {
    __syncthreads();
    if (threadIdx.x == 0) {
        unsigned gen0;
        asm volatile("ld.acquire.gpu.u32 %0, [%1];" : "=r"(gen0) : "l"(&g_bar_gen));
        unsigned prev;
        asm volatile("atom.release.gpu.global.add.u32 %0, [%1], 1;" : "=r"(prev) : "l"(&g_bar_cnt));
        if (prev == NBLK - 1) {
            asm volatile("st.relaxed.gpu.global.u32 [%0], 0;" :: "l"(&g_bar_cnt));
            asm volatile("red.release.gpu.global.add.u32 [%0], 1;" :: "l"(&g_bar_gen));
        } else {
            unsigned g;
            do { asm volatile("ld.acquire.gpu.u32 %0, [%1];" : "=r"(g) : "l"(&g_bar_gen)); } while (g == gen0);
        }
    }
    __syncthreads();
}

// pack one unit (b, u0+uu): hi at poff, lo at poff+512 (R13-verified layout)
__device__ __forceinline__ void pack_unit(char* bufbase, uint32_t off, float v) {
    __nv_bfloat16 h = __float2bfloat16(v);
    __nv_bfloat16 lo = __float2bfloat16(v - __bfloat162float(h));
    *(unsigned short*)(bufbase + off)       = __bfloat16_as_ushort(h);
    *(unsigned short*)(bufbase + off + 512) = __bfloat16_as_ushort(lo);
}

__global__ void __launch_bounds__(NT, 1)
gru_all(const int* __restrict__ x, const float* __restrict__ hidden,
        const float* __restrict__ Win, const float* __restrict__ Wrec,
        const float* __restrict__ bin, const float* __restrict__ brec,
        float* __restrict__ out) {
    extern __shared__ __align__(1024) char smem[];
    const uint32_t sbase = smem_u32(smem);
    const int tid = threadIdx.x;
    const int wid = tid >> 5;
    const int l   = tid & 31;
    const int blk = blockIdx.x;
    const int u0  = blk * 8;

    // ---- one-time: W_rec slice -> bf16 hi/lo in SMEM [pass][n][k] ----
    for (int idx = tid; idx < 24 * U; idx += NT) {
        int k = idx / 24;
        int j = idx - k * 24;
        int gate = j >> 3, uu = j & 7;
        float w = Wrec[(size_t)k * G3 + gate * U + u0 + uu];
        __nv_bfloat16 hi = __float2bfloat16(w);
        __nv_bfloat16 lo = __float2bfloat16(w - __bfloat162float(hi));
        *(__nv_bfloat16*)(smem + SM_W + j * W_NSTR + k * 2) = hi;
        *(__nv_bfloat16*)(smem + SM_W + W_PSTR + j * W_NSTR + k * 2) = lo;
    }

    // ---- gate mapping: 512 threads, 1 unit each: (b = tid>>3, uu) ----
    // threads 0..255 are group 0 (b 0..31), 256..511 group 1 (b 32..63)
    const int b   = tid >> 3;
    const int uu  = tid & 7;
    const int bth = tid >> 8;            // gate-side group
    const int btg = b >> 4, r_ = b & 15;
    const int kk_self = u0 >> 4;
    const uint32_t woff = (uint32_t)((r_ & 7) * 4 + ((uu >> 1) & 3)) * 16
                        + (uint32_t)((r_ >> 3) + 2 * ((u0 >> 3) & 1)) * 4
                        + (uu & 1) * 2;
    const uint32_t poff = (uint32_t)((btg * 64 + kk_self) * 2) * 512 + woff;

    const float cz  = bin[0 * U + u0 + uu] + brec[0 * U + u0 + uu];
    const float cr  = bin[1 * U + u0 + uu] + brec[1 * U + u0 + uu];
    const float bih = bin[2 * U + u0 + uu];
    const float bhh = brec[2 * U + u0 + uu];
    float hold = hidden[(size_t)b * U + u0 + uu];
    int tok = x[b * T];

    // ---- warp MMA mapping: group bth = wid>>3 (matches gate group),
    //      kq = wid&7 (k-eighth); bt tiles {2*bth, 2*bth+1} ----
    const int kq = wid & 7;
    const uint32_t boff4 = (uint32_t)((l >> 4) * 8 + (l & 7)) * W_NSTR + ((l >> 3) & 1) * 16;
    const uint32_t boff2 = (uint32_t)(l & 7) * W_NSTR + (l & 8) * 2;
    const int grp = blk >> 4;                 // producer k-eighth
    const int fc  = kq * 2 + bth;             // consumer flag index
    const int fp  = grp * 2 + bth;            // producer flag index
    float* recg = (float*)(smem + SM_REC + bth * REC_GRP);

    unsigned fbase = *(volatile unsigned*)&g_flag[fc * 32];
    grid_barrier();

    // publish h0 into buffer 0; per-group arrival
    pack_unit((char*)g_hpk[0], poff, hold);
    grid_barrier();   // simple race-free init for step 0 (one-time cost)
    if (tid == 0)   arrive_flag(&g_flag[(grp * 2 + 0) * 32]);
    if (tid == 256) arrive_flag(&g_flag[(grp * 2 + 1) * 32]);

    for (int t = 0; t < T; t++) {
        const int par = t & 1;

        // gate-input loads issued before the flag wait
        const float* wrow = Win + (size_t)tok * G3 + u0 + uu;
        float xz = wrow[0], xr = wrow[U], xh = wrow[2 * U];
        int tok_n = (t + 1 < T) ? x[b * T + t + 1] : 0;

        // wait for the 16 producer CTAs of (this k-eighth, this group)
        if (l == 0) wait_flag(&g_flag[fc * 32], fbase + 16u * (t + 1));
        __syncwarp();

        // ---- GEMM: 8 k-tiles, 2 batch-tiles of this group ----
        float acc[2][3][4];
        #pragma unroll
        for (int bt = 0; bt < 2; bt++)
            #pragma unroll
            for (int nt = 0; nt < 3; nt++)
                #pragma unroll
                for (int e = 0; e < 4; e++) acc[bt][nt][e] = 0.f;

        const uint4* pA0 = g_hpk[par] + (size_t)(((2 * bth)     * 64 + kq * 8) * 2) * 32 + l;
        const uint4* pA1 = g_hpk[par] + (size_t)(((2 * bth + 1) * 64 + kq * 8) * 2) * 32 + l;

        uint4 Ah[2][2], Al[2][2];
        #pragma unroll
        for (int i = 0; i < 2; i++) {
            Ah[0][i] = __ldcg(pA0 + i * 64); Al[0][i] = __ldcg(pA0 + i * 64 + 32);
            Ah[1][i] = __ldcg(pA1 + i * 64); Al[1][i] = __ldcg(pA1 + i * 64 + 32);
        }

        #pragma unroll
        for (int kt = 0; kt < 8; kt++) {
            uint32_t wb = sbase + SM_W + (uint32_t)(kq * 8 + kt) * 32;
            uint32_t bh01[4], bl01[4], bh2[2], bl2[2];
            ldsm4(bh01, wb + boff4);
            ldsm2(bh2,  wb + 16 * W_NSTR + boff2);
            ldsm4(bl01, wb + W_PSTR + boff4);
            ldsm2(bl2,  wb + W_PSTR + 16 * W_NSTR + boff2);

            uint4 c0h = Ah[0][kt & 1], c0l = Al[0][kt & 1];
            uint4 c1h = Ah[1][kt & 1], c1l = Al[1][kt & 1];
            if (kt < 6) {
                Ah[0][kt & 1] = __ldcg(pA0 + (kt + 2) * 64);
                Al[0][kt & 1] = __ldcg(pA0 + (kt + 2) * 64 + 32);
                Ah[1][kt & 1] = __ldcg(pA1 + (kt + 2) * 64);
                Al[1][kt & 1] = __ldcg(pA1 + (kt + 2) * 64 + 32);
            }

            mma4(acc[0][0], c0h, bh01[0], bh01[1]);
            mma4(acc[0][1], c0h, bh01[2], bh01[3]);
            mma4(acc[0][2], c0h, bh2[0],  bh2[1]);
            mma4(acc[1][0], c1h, bh01[0], bh01[1]);
            mma4(acc[1][1], c1h, bh01[2], bh01[3]);
            mma4(acc[1][2], c1h, bh2[0],  bh2[1]);

            mma4(acc[0][0], c0h, bl01[0], bl01[1]);
            mma4(acc[0][1], c0h, bl01[2], bl01[3]);
            mma4(acc[0][2], c0h, bl2[0],  bl2[1]);
            mma4(acc[1][0], c1h, bl01[0], bl01[1]);
            mma4(acc[1][1], c1h, bl01[2], bl01[3]);
            mma4(acc[1][2], c1h, bl2[0],  bl2[1]);

            mma4(acc[0][0], c0l, bh01[0], bh01[1]);
            mma4(acc[0][1], c0l, bh01[2], bh01[3]);
            mma4(acc[0][2], c0l, bh2[0],  bh2[1]);
            mma4(acc[1][0], c1l, bh01[0], bh01[1]);
            mma4(acc[1][1], c1l, bh01[2], bh01[3]);
            mma4(acc[1][2], c1l, bh2[0],  bh2[1]);
        }

        // ---- epilogue: partials -> this group's plane kq ----
        {
            float* pl = recg + kq * REC_PL;
            int row = l >> 2, c2 = (l & 3) * 2;
            #pragma unroll
            for (int bt = 0; bt < 2; bt++) {
                int bb0 = bt * 16 + row;   // group-local row 0..31
                #pragma unroll
                for (int nt = 0; nt < 3; nt++) {
                    int j0 = nt * 8 + c2;
                    *(float2*)&pl[bb0 * 26 + j0]       = make_float2(acc[bt][nt][0], acc[bt][nt][1]);
                    *(float2*)&pl[(bb0 + 8) * 26 + j0] = make_float2(acc[bt][nt][2], acc[bt][nt][3]);
                }
            }
        }
        // group-local barrier (256 threads, id 1 or 2)
        if (bth == 0) asm volatile("bar.sync 1, 256;" ::: "memory");
        else          asm volatile("bar.sync 2, 256;" ::: "memory");

        // ---- gates: 1 unit per thread (group-local rows) ----
        {
            float rz = cz, rr = cr, rh = bhh;
            const int lb = b & 31;
            #pragma unroll
            for (int p = 0; p < 8; p++) {
                const float* pl = recg + p * REC_PL + lb * 26;
                rz += pl[uu];
                rr += pl[8 + uu];
                rh += pl[16 + uu];
            }
            float z  = __fdividef(1.f, 1.f + __expf(-(xz + rz)));
            float r  = __fdividef(1.f, 1.f + __expf(-(xr + rr)));
            float ta = xh + bih + r * rh;
            float hh = 1.f - __fdividef(2.f, __expf(2.f * ta) + 1.f);
            float hn = z * hold + (1.f - z) * hh;
            hold = hn;
            pack_unit((char*)g_hpk[par ^ 1], poff, hn);
            // group-local barrier: all packs done + plane reads done
            if (bth == 0) asm volatile("bar.sync 1, 256;" ::: "memory");
            else          asm volatile("bar.sync 2, 256;" ::: "memory");
            if ((tid == 0 || tid == 256) && t < T - 1)
                arrive_flag(&g_flag[fp * 32]);
            out[((size_t)b * T + t) * U + u0 + uu] = hn;
            if (t == T - 1)
                out[(size_t)B * T * U + (size_t)b * U + u0 + uu] = hn;
            tok = tok_n;
        }
    }
}

extern "C" void kernel_launch(void* const* d_in, const int* in_sizes, int n_in,
                              void* d_out, int out_size) {
    const int*   x      = (const int*)d_in[0];
    const float* hidden = (const float*)d_in[1];
    const float* Win    = (const float*)d_in[2];
    const float* Wrec   = (const float*)d_in[3];
    const float* bin    = (const float*)d_in[4];
    const float* brec   = (const float*)d_in[5];
    float* out = (float*)d_out;

    cudaFuncSetAttribute(gru_all, cudaFuncAttributeMaxDynamicSharedMemorySize, SMEM_TOTAL);
    gru_all<<<NBLK, NT, SMEM_TOTAL>>>(x, hidden, Win, Wrec, bin, brec, out);
}